// round 2
// baseline (speedup 1.0000x reference)
#include <cuda_runtime.h>
#include <math.h>

// Problem constants
#define NB   32      // batch
#define TE   512     // encoder time
#define LD   128     // decoder length
#define VV   8000    // vocab
#define EE   256     // embed
#define HH   1024    // hidden1
#define KSZ  128     // hidden2 / key size
#define VSZ  128     // value size
#define G1   4096    // 4*H
#define G2   512     // 4*KS
#define KT   1152    // ctx(128)+h1(1024)  (also h1(1024)+h2(128) for lstm2)

// ---------------- device scratch (static, no allocations) ----------------
__device__ float g_X[(LD*NB)*EE];          // 4 MB   embedded inputs, row = t*32+n
__device__ float g_Xg[(LD*NB)*G1];         // 67 MB  precomputed x@W_ih1[:, :256]^T + biases
__device__ float g_act[NB*KT];             // per-n: [0:128)=ctx, [128:1152)=h1
__device__ float g_h2[NB*KSZ];
__device__ float g_c1[NB*HH];
__device__ float g_c2[NB*KSZ];
__device__ float g_part1[4*NB*G1];         // 2 MB   lstm1 split-K partials
__device__ float g_part2[16*NB*G2];        // 1 MB   lstm2 split-K partials
__device__ float g_h2ctx[(LD*NB)*256];     // 4 MB   [h2, ctx] per (t,n)

__device__ __forceinline__ float sigm(float x){ return 1.0f/(1.0f + expf(-x)); }

// ---------------- init: embed gather + state init ----------------
__global__ __launch_bounds__(256) void kInit(const int* __restrict__ text,
                                             const float* __restrict__ emb,
                                             const float* __restrict__ values)
{
    int b = blockIdx.x, tid = threadIdx.x;
    if (b < LD*NB) {
        int t = b >> 5, n = b & 31;
        int idx = (t == 0) ? 1 : text[n*LD + (t-1)];
        g_X[b*EE + tid] = emb[idx*EE + tid];
    } else {
        int i = (b - LD*NB)*256 + tid;
        if (i < 32768) { g_c1[i] = 0.f; }
        else if (i < 65536) { int u = i - 32768; int n = u >> 10, uu = u & 1023; g_act[n*KT + 128 + uu] = 0.f; }
        else if (i < 69632) { g_c2[i - 65536] = 0.f; }
        else if (i < 73728) { g_h2[i - 69632] = 0.f; }
        else if (i < 77824) { int u = i - 73728; int n = u >> 7, k = u & 127;
                              g_act[n*KT + k] = values[n*(TE*VSZ) + k]; }  // values[n,0,:]
    }
}

// ---------------- big GEMM: C[M x Nc] = A[M x 256] * B[Nc x 256(ldb)]^T (+bias) ----------------
// MODE 0: C row-major (Xg), bias = bias1[j]+bias2[j]
// MODE 1: output logits: row r -> (n=r&31, t=r>>5), write out[(n*LD+t)*Nc + j], bias = bias1[j]
template<int LDB, int MODE>
__global__ __launch_bounds__(256) void kGemmBig(const float* __restrict__ A,
                                                const float* __restrict__ B,
                                                const float* __restrict__ bias1,
                                                const float* __restrict__ bias2,
                                                float* __restrict__ C, int Nc)
{
    __shared__ float As[16][132];
    __shared__ float Bs[16][68];
    int tid = threadIdx.x;
    int m_base = blockIdx.y * 128;
    int n_base = blockIdx.x * 64;
    int tm = tid & 15, tn = tid >> 4;
    int m0 = tm*8, n0 = tn*4;
    float acc[8][4];
#pragma unroll
    for (int i=0;i<8;i++)
#pragma unroll
        for (int j=0;j<4;j++) acc[i][j]=0.f;

    int a_row = tid >> 1, a_kq = (tid & 1)*8;
    int b_row = tid >> 2, b_kq = (tid & 3)*4;

    for (int kc = 0; kc < 256; kc += 16) {
        float4 a0 = *(const float4*)&A[(m_base + a_row)*256 + kc + a_kq];
        float4 a1 = *(const float4*)&A[(m_base + a_row)*256 + kc + a_kq + 4];
        float4 b0 = *(const float4*)&B[(n_base + b_row)*LDB + kc + b_kq];
        __syncthreads();
        As[a_kq+0][a_row]=a0.x; As[a_kq+1][a_row]=a0.y; As[a_kq+2][a_row]=a0.z; As[a_kq+3][a_row]=a0.w;
        As[a_kq+4][a_row]=a1.x; As[a_kq+5][a_row]=a1.y; As[a_kq+6][a_row]=a1.z; As[a_kq+7][a_row]=a1.w;
        Bs[b_kq+0][b_row]=b0.x; Bs[b_kq+1][b_row]=b0.y; Bs[b_kq+2][b_row]=b0.z; Bs[b_kq+3][b_row]=b0.w;
        __syncthreads();
#pragma unroll
        for (int kk = 0; kk < 16; kk++) {
            float4 av0 = *(const float4*)&As[kk][m0];
            float4 av1 = *(const float4*)&As[kk][m0+4];
            float4 bv  = *(const float4*)&Bs[kk][n0];
            float a8[8] = {av0.x,av0.y,av0.z,av0.w,av1.x,av1.y,av1.z,av1.w};
            float b4[4] = {bv.x,bv.y,bv.z,bv.w};
#pragma unroll
            for (int i=0;i<8;i++)
#pragma unroll
                for (int j=0;j<4;j++) acc[i][j] = fmaf(a8[i], b4[j], acc[i][j]);
        }
    }

    float bb[4];
#pragma unroll
    for (int j=0;j<4;j++) {
        int gj = n_base + n0 + j;
        bb[j] = bias1[gj] + (MODE==0 ? bias2[gj] : 0.f);
    }
#pragma unroll
    for (int i=0;i<8;i++) {
        int r = m_base + m0 + i;
        float4 v = make_float4(acc[i][0]+bb[0], acc[i][1]+bb[1], acc[i][2]+bb[2], acc[i][3]+bb[3]);
        if (MODE == 0) {
            *(float4*)&C[r*Nc + n_base + n0] = v;
        } else {
            int n = r & 31, t = r >> 5;
            *(float4*)&C[(n*LD + t)*Nc + n_base + n0] = v;
        }
    }
}

// ---------------- per-step LSTM1 GEMM: partials over K slice of 288 ----------------
// gates_part[s][n][j] = sum_{k in slice} act[n][k] * W(j,k)
//   k<128 : ctx  -> W_ih1[j*384 + 256 + k]
//   k>=128: h1   -> W_hh1[j*1024 + (k-128)]
__global__ __launch_bounds__(256) void kLstm1Gemm(const float* __restrict__ W_ih1,
                                                  const float* __restrict__ W_hh1)
{
    __shared__ float As[16][36];
    __shared__ float Ws[16][132];
    int tid = threadIdx.x;
    int jb = blockIdx.x * 128;
    int s  = blockIdx.y;
    int k_start = s * 288;
    int tm = tid & 7, tn = tid >> 3;
    int m0 = tm*4, n0 = tn*4;
    float acc[4][4];
#pragma unroll
    for (int i=0;i<4;i++)
#pragma unroll
        for (int j=0;j<4;j++) acc[i][j]=0.f;

    int an = tid >> 3, ak = (tid & 7)*2;
    int wj = tid >> 1, wkg = (tid & 1)*8;

    for (int kc = k_start; kc < k_start + 288; kc += 16) {
        float2 av = *(const float2*)&g_act[an*KT + kc + ak];
        int kg0 = kc + wkg;
        float4 w0, w1;
        if (kg0 < 128) {
            const float* p = &W_ih1[(jb+wj)*384 + 256 + kg0];
            w0 = *(const float4*)p; w1 = *(const float4*)(p+4);
        } else {
            const float* p = &W_hh1[(jb+wj)*1024 + (kg0-128)];
            w0 = *(const float4*)p; w1 = *(const float4*)(p+4);
        }
        __syncthreads();
        As[ak][an]   = av.x;
        As[ak+1][an] = av.y;
        Ws[wkg+0][wj]=w0.x; Ws[wkg+1][wj]=w0.y; Ws[wkg+2][wj]=w0.z; Ws[wkg+3][wj]=w0.w;
        Ws[wkg+4][wj]=w1.x; Ws[wkg+5][wj]=w1.y; Ws[wkg+6][wj]=w1.z; Ws[wkg+7][wj]=w1.w;
        __syncthreads();
#pragma unroll
        for (int kk = 0; kk < 16; kk++) {
            float4 a4 = *(const float4*)&As[kk][m0];
            float4 b4 = *(const float4*)&Ws[kk][n0];
            float aa[4]={a4.x,a4.y,a4.z,a4.w};
            float bbv[4]={b4.x,b4.y,b4.z,b4.w};
#pragma unroll
            for (int i=0;i<4;i++)
#pragma unroll
                for (int j=0;j<4;j++) acc[i][j] = fmaf(aa[i], bbv[j], acc[i][j]);
        }
    }
#pragma unroll
    for (int i=0;i<4;i++) {
        float4 v = make_float4(acc[i][0],acc[i][1],acc[i][2],acc[i][3]);
        *(float4*)&g_part1[(s*NB + m0 + i)*G1 + jb + n0] = v;
    }
}

// ---------------- cell1: reduce partials + LSTM cell, writes h1 into g_act ----------------
__global__ __launch_bounds__(256) void kCell1(int t)
{
    int id = blockIdx.x*256 + threadIdx.x;   // < 32768
    int n = id >> 10, u = id & 1023;
    const float* xg = &g_Xg[(t*NB + n)*G1];
    float gi = xg[u], gf = xg[u+1024], gg = xg[u+2048], go = xg[u+3072];
#pragma unroll
    for (int s=0;s<4;s++) {
        const float* p = &g_part1[(s*NB + n)*G1];
        gi += p[u]; gf += p[u+1024]; gg += p[u+2048]; go += p[u+3072];
    }
    float i_ = sigm(gi), f_ = sigm(gf), g_ = tanhf(gg), o_ = sigm(go);
    float c = f_*g_c1[id] + i_*g_;
    g_c1[id] = c;
    g_act[n*KT + 128 + u] = o_*tanhf(c);
}

// ---------------- per-step LSTM2 GEMM partials (16 splits of 72) ----------------
//   k<1024 : h1 -> W_ih2[j*1024 + k], act = g_act[n][128+k]
//   k>=1024: h2 -> W_hh2[j*128 + (k-1024)], act = g_h2[n][k-1024]
__global__ __launch_bounds__(128) void kLstm2Gemm(const float* __restrict__ W_ih2,
                                                  const float* __restrict__ W_hh2)
{
    __shared__ float As[8][36];
    __shared__ float Ws[8][68];
    int tid = threadIdx.x;
    int jb = blockIdx.x * 64;
    int s  = blockIdx.y;
    int k0s = s * 72;
    int tm = tid & 7, tn = tid >> 3;
    int m0 = tm*4, n0 = tn*4;
    float acc[4][4];
#pragma unroll
    for (int i=0;i<4;i++)
#pragma unroll
        for (int j=0;j<4;j++) acc[i][j]=0.f;

    int an = tid >> 2, ak = (tid & 3)*2;
    int wj = tid >> 1, wk = (tid & 1)*4;

    for (int kc = k0s; kc < k0s + 72; kc += 8) {
        int ka = kc + ak;
        float2 av = (ka < 1024) ? *(const float2*)&g_act[an*KT + 128 + ka]
                                : *(const float2*)&g_h2[an*KSZ + ka - 1024];
        int kw = kc + wk;
        float4 wv = (kw < 1024) ? *(const float4*)&W_ih2[(jb+wj)*1024 + kw]
                                : *(const float4*)&W_hh2[(jb+wj)*128 + kw - 1024];
        __syncthreads();
        As[ak][an]   = av.x;
        As[ak+1][an] = av.y;
        Ws[wk+0][wj]=wv.x; Ws[wk+1][wj]=wv.y; Ws[wk+2][wj]=wv.z; Ws[wk+3][wj]=wv.w;
        __syncthreads();
#pragma unroll
        for (int kk = 0; kk < 8; kk++) {
            float4 a4 = *(const float4*)&As[kk][m0];
            float4 b4 = *(const float4*)&Ws[kk][n0];
            float aa[4]={a4.x,a4.y,a4.z,a4.w};
            float bbv[4]={b4.x,b4.y,b4.z,b4.w};
#pragma unroll
            for (int i=0;i<4;i++)
#pragma unroll
                for (int j=0;j<4;j++) acc[i][j] = fmaf(aa[i], bbv[j], acc[i][j]);
        }
    }
#pragma unroll
    for (int i=0;i<4;i++) {
        float4 v = make_float4(acc[i][0],acc[i][1],acc[i][2],acc[i][3]);
        *(float4*)&g_part2[(s*NB + m0 + i)*G2 + jb + n0] = v;
    }
}

// ---------------- cell2 + attention (one block per batch row) ----------------
__global__ __launch_bounds__(256) void kCell2Attn(int t,
                                                  const float* __restrict__ key,
                                                  const float* __restrict__ values,
                                                  const int* __restrict__ enc_lens,
                                                  const float* __restrict__ b_ih2,
                                                  const float* __restrict__ b_hh2)
{
    int n = blockIdx.x, tid = threadIdx.x;
    __shared__ float h2s[128];
    __shared__ float es[512];
    __shared__ float red[256];
    __shared__ float cs[2][128];

    if (tid < 128) {
        int u = tid;
        float g4[4];
#pragma unroll
        for (int g = 0; g < 4; g++) {
            int j = g*128 + u;
            float a = b_ih2[j] + b_hh2[j];
#pragma unroll
            for (int s = 0; s < 16; s++) a += g_part2[(s*NB + n)*G2 + j];
            g4[g] = a;
        }
        float i_ = sigm(g4[0]), f_ = sigm(g4[1]), gg = tanhf(g4[2]), o_ = sigm(g4[3]);
        float c = f_*g_c2[n*KSZ + u] + i_*gg;
        g_c2[n*KSZ + u] = c;
        float h = o_*tanhf(c);
        h2s[u] = h;
        g_h2[n*KSZ + u] = h;
    }
    __syncthreads();

    int warp = tid >> 5, lane = tid & 31;
    int len = enc_lens[n];
    const float4* h24 = (const float4*)h2s;
    float4 hv = h24[lane];
    for (int te = warp; te < TE; te += 8) {
        const float4* kp = (const float4*)&key[(n*TE + te)*KSZ];
        float4 kv = kp[lane];
        float p = kv.x*hv.x + kv.y*hv.y + kv.z*hv.z + kv.w*hv.w;
        p += __shfl_xor_sync(0xffffffffu, p, 16);
        p += __shfl_xor_sync(0xffffffffu, p, 8);
        p += __shfl_xor_sync(0xffffffffu, p, 4);
        p += __shfl_xor_sync(0xffffffffu, p, 2);
        p += __shfl_xor_sync(0xffffffffu, p, 1);
        if (lane == 0) es[te] = (te >= len) ? -1.0e9f : p;
    }
    __syncthreads();

    // softmax over 512
    float m = fmaxf(es[tid], es[tid + 256]);
    red[tid] = m;
    __syncthreads();
    for (int st = 128; st > 0; st >>= 1) {
        if (tid < st) red[tid] = fmaxf(red[tid], red[tid + st]);
        __syncthreads();
    }
    float mx = red[0];
    __syncthreads();
    float p0 = expf(es[tid] - mx);
    float p1 = expf(es[tid + 256] - mx);
    es[tid] = p0; es[tid + 256] = p1;
    red[tid] = p0 + p1;
    __syncthreads();
    for (int st = 128; st > 0; st >>= 1) {
        if (tid < st) red[tid] += red[tid + st];
        __syncthreads();
    }
    float inv = 1.0f / red[0];

    // context: ctx[v] = inv * sum_t es[t] * values[n][t][v]
    int v = tid & 127, half = tid >> 7;
    float acc = 0.f;
    int tb = half * 256;
#pragma unroll 4
    for (int te = tb; te < tb + 256; te++)
        acc += es[te] * values[(n*TE + te)*VSZ + v];
    cs[half][v] = acc;
    __syncthreads();
    if (tid < 128) {
        float ctx = (cs[0][tid] + cs[1][tid]) * inv;
        g_act[n*KT + tid] = ctx;
        float* hc = &g_h2ctx[(t*NB + n)*256];
        hc[tid]       = h2s[tid];
        hc[128 + tid] = ctx;
    }
}

// ---------------- launch ----------------
extern "C" void kernel_launch(void* const* d_in, const int* in_sizes, int n_in,
                              void* d_out, int out_size)
{
    const float* key    = (const float*)d_in[0];
    const float* values = (const float*)d_in[1];
    const int*   elens  = (const int*)  d_in[2];
    const int*   text   = (const int*)  d_in[3];
    const float* emb    = (const float*)d_in[4];
    const float* W_ih1  = (const float*)d_in[5];
    const float* W_hh1  = (const float*)d_in[6];
    const float* b_ih1  = (const float*)d_in[7];
    const float* b_hh1  = (const float*)d_in[8];
    const float* W_ih2  = (const float*)d_in[9];
    const float* W_hh2  = (const float*)d_in[10];
    const float* b_ih2  = (const float*)d_in[11];
    const float* b_out  = (const float*)d_in[14];
    const float* W_out  = (const float*)d_in[13];
    const float* b_hh2  = (const float*)d_in[12];
    float* out = (float*)d_out;

    // init: 4096 blocks for embedding + 304 blocks for state init
    kInit<<<LD*NB + 304, 256>>>(text, emb, values);

    // precompute Xg = X @ W_ih1[:, :256]^T + b_ih1 + b_hh1
    {
        float* gXg; cudaGetSymbolAddress((void**)&gXg, g_Xg);
        float* gX;  cudaGetSymbolAddress((void**)&gX, g_X);
        kGemmBig<384,0><<<dim3(G1/64, (LD*NB)/128), 256>>>(gX, W_ih1, b_ih1, b_hh1, gXg, G1);
    }

    for (int t = 0; t < LD; t++) {
        kLstm1Gemm<<<dim3(32, 4), 256>>>(W_ih1, W_hh1);
        kCell1<<<128, 256>>>(t);
        kLstm2Gemm<<<dim3(8, 16), 128>>>(W_ih2, W_hh2);
        kCell2Attn<<<32, 256>>>(t, key, values, elens, b_ih2, b_hh2);
    }

    // output logits: [h2,ctx] @ W_out^T + b_out, remapped to (n, t, v)
    {
        float* gHC; cudaGetSymbolAddress((void**)&gHC, g_h2ctx);
        kGemmBig<256,1><<<dim3(VV/64, (LD*NB)/128), 256>>>(gHC, W_out, b_out, (const float*)0, out, VV);
    }
}

// round 3
// speedup vs baseline: 1.0400x; 1.0400x over previous
#include <cuda_runtime.h>
#include <math.h>

// Problem constants
#define NB   32      // batch
#define TE   512     // encoder time
#define LD   128     // decoder length
#define VV   8000    // vocab
#define EE   256     // embed
#define HH   1024    // hidden1
#define KSZ  128     // hidden2 / key size
#define VSZ  128     // value size
#define G1   4096    // 4*H
#define G2   512     // 4*KS
#define KT   1152    // ctx(128)+h1(1024)  (also h1(1024)+h2(128) for lstm2)

// ---------------- device scratch (static, no allocations) ----------------
__device__ float g_X[(LD*NB)*EE];          // 4 MB   embedded inputs, row = t*32+n
__device__ float g_Xg[(LD*NB)*G1];         // 67 MB  precomputed x@W_ih1[:, :256]^T + biases
__device__ float g_act[NB*KT];             // per-n: [0:128)=ctx, [128:1152)=h1
__device__ float g_h2[NB*KSZ];
__device__ float g_c1[NB*HH];
__device__ float g_c2[NB*KSZ];
__device__ float g_part1[4*NB*G1];         // 2 MB   lstm1 split-K partials
__device__ float g_part2[16*NB*G2];        // 1 MB   lstm2 split-K partials
__device__ float g_h2ctx[(LD*NB)*256];     // 4 MB   [h2, ctx] per (t,n)

__device__ __forceinline__ float sigm(float x){ return 1.0f/(1.0f + expf(-x)); }

// ---------------- init: embed gather + state init ----------------
__global__ __launch_bounds__(256) void kInit(const int* __restrict__ text,
                                             const float* __restrict__ emb,
                                             const float* __restrict__ values)
{
    int b = blockIdx.x, tid = threadIdx.x;
    if (b < LD*NB) {
        int t = b >> 5, n = b & 31;
        int idx = (t == 0) ? 1 : text[n*LD + (t-1)];
        g_X[b*EE + tid] = emb[idx*EE + tid];
    } else {
        int i = (b - LD*NB)*256 + tid;
        if (i < 32768) { g_c1[i] = 0.f; }
        else if (i < 65536) { int u = i - 32768; int n = u >> 10, uu = u & 1023; g_act[n*KT + 128 + uu] = 0.f; }
        else if (i < 69632) { g_c2[i - 65536] = 0.f; }
        else if (i < 73728) { g_h2[i - 69632] = 0.f; }
        else if (i < 77824) { int u = i - 73728; int n = u >> 7, k = u & 127;
                              g_act[n*KT + k] = values[n*(TE*VSZ) + k]; }  // values[n,0,:]
    }
}

// ---------------- big GEMM: C[M x Nc] = A[M x 256] * B[Nc x 256(ldb)]^T (+bias) ----------------
// MODE 0: C row-major (Xg), bias = bias1[j]+bias2[j]
// MODE 1: output logits: row r -> (n=r&31, t=r>>5), write out[(n*LD+t)*Nc + j], bias = bias1[j]
template<int LDB, int MODE>
__global__ __launch_bounds__(256) void kGemmBig(const float* __restrict__ A,
                                                const float* __restrict__ B,
                                                const float* __restrict__ bias1,
                                                const float* __restrict__ bias2,
                                                float* __restrict__ C, int Nc)
{
    __shared__ float As[16][132];
    __shared__ float Bs[16][68];
    int tid = threadIdx.x;
    int m_base = blockIdx.y * 128;
    int n_base = blockIdx.x * 64;
    int tm = tid & 15, tn = tid >> 4;
    int m0 = tm*8, n0 = tn*4;
    float acc[8][4];
#pragma unroll
    for (int i=0;i<8;i++)
#pragma unroll
        for (int j=0;j<4;j++) acc[i][j]=0.f;

    int a_row = tid >> 1, a_kq = (tid & 1)*8;
    int b_row = tid >> 2, b_kq = (tid & 3)*4;

    for (int kc = 0; kc < 256; kc += 16) {
        float4 a0 = *(const float4*)&A[(m_base + a_row)*256 + kc + a_kq];
        float4 a1 = *(const float4*)&A[(m_base + a_row)*256 + kc + a_kq + 4];
        float4 b0 = *(const float4*)&B[(n_base + b_row)*LDB + kc + b_kq];
        __syncthreads();
        As[a_kq+0][a_row]=a0.x; As[a_kq+1][a_row]=a0.y; As[a_kq+2][a_row]=a0.z; As[a_kq+3][a_row]=a0.w;
        As[a_kq+4][a_row]=a1.x; As[a_kq+5][a_row]=a1.y; As[a_kq+6][a_row]=a1.z; As[a_kq+7][a_row]=a1.w;
        Bs[b_kq+0][b_row]=b0.x; Bs[b_kq+1][b_row]=b0.y; Bs[b_kq+2][b_row]=b0.z; Bs[b_kq+3][b_row]=b0.w;
        __syncthreads();
#pragma unroll
        for (int kk = 0; kk < 16; kk++) {
            float4 av0 = *(const float4*)&As[kk][m0];
            float4 av1 = *(const float4*)&As[kk][m0+4];
            float4 bv  = *(const float4*)&Bs[kk][n0];
            float a8[8] = {av0.x,av0.y,av0.z,av0.w,av1.x,av1.y,av1.z,av1.w};
            float b4[4] = {bv.x,bv.y,bv.z,bv.w};
#pragma unroll
            for (int i=0;i<8;i++)
#pragma unroll
                for (int j=0;j<4;j++) acc[i][j] = fmaf(a8[i], b4[j], acc[i][j]);
        }
    }

    float bb[4];
#pragma unroll
    for (int j=0;j<4;j++) {
        int gj = n_base + n0 + j;
        bb[j] = bias1[gj] + (MODE==0 ? bias2[gj] : 0.f);
    }
#pragma unroll
    for (int i=0;i<8;i++) {
        int r = m_base + m0 + i;
        float4 v = make_float4(acc[i][0]+bb[0], acc[i][1]+bb[1], acc[i][2]+bb[2], acc[i][3]+bb[3]);
        if (MODE == 0) {
            *(float4*)&C[r*Nc + n_base + n0] = v;
        } else {
            int n = r & 31, t = r >> 5;
            *(float4*)&C[(n*LD + t)*Nc + n_base + n0] = v;
        }
    }
}

// ---------------- per-step LSTM1 GEMM: partials over K slice of 288 ----------------
// gates_part[s][n][j] = sum_{k in slice} act[n][k] * W(j,k)
//   k<128 : ctx  -> W_ih1[j*384 + 256 + k]
//   k>=128: h1   -> W_hh1[j*1024 + (k-128)]
__global__ __launch_bounds__(256) void kLstm1Gemm(const float* __restrict__ W_ih1,
                                                  const float* __restrict__ W_hh1)
{
    __shared__ float As[16][36];
    __shared__ float Ws[16][132];
    int tid = threadIdx.x;
    int jb = blockIdx.x * 128;
    int s  = blockIdx.y;
    int k_start = s * 288;
    int tm = tid & 7, tn = tid >> 3;
    int m0 = tm*4, n0 = tn*4;
    float acc[4][4];
#pragma unroll
    for (int i=0;i<4;i++)
#pragma unroll
        for (int j=0;j<4;j++) acc[i][j]=0.f;

    int an = tid >> 3, ak = (tid & 7)*2;
    int wj = tid >> 1, wkg = (tid & 1)*8;

    for (int kc = k_start; kc < k_start + 288; kc += 16) {
        float2 av = *(const float2*)&g_act[an*KT + kc + ak];
        int kg0 = kc + wkg;
        float4 w0, w1;
        if (kg0 < 128) {
            const float* p = &W_ih1[(jb+wj)*384 + 256 + kg0];
            w0 = *(const float4*)p; w1 = *(const float4*)(p+4);
        } else {
            const float* p = &W_hh1[(jb+wj)*1024 + (kg0-128)];
            w0 = *(const float4*)p; w1 = *(const float4*)(p+4);
        }
        __syncthreads();
        As[ak][an]   = av.x;
        As[ak+1][an] = av.y;
        Ws[wkg+0][wj]=w0.x; Ws[wkg+1][wj]=w0.y; Ws[wkg+2][wj]=w0.z; Ws[wkg+3][wj]=w0.w;
        Ws[wkg+4][wj]=w1.x; Ws[wkg+5][wj]=w1.y; Ws[wkg+6][wj]=w1.z; Ws[wkg+7][wj]=w1.w;
        __syncthreads();
#pragma unroll
        for (int kk = 0; kk < 16; kk++) {
            float4 a4 = *(const float4*)&As[kk][m0];
            float4 b4 = *(const float4*)&Ws[kk][n0];
            float aa[4]={a4.x,a4.y,a4.z,a4.w};
            float bbv[4]={b4.x,b4.y,b4.z,b4.w};
#pragma unroll
            for (int i=0;i<4;i++)
#pragma unroll
                for (int j=0;j<4;j++) acc[i][j] = fmaf(aa[i], bbv[j], acc[i][j]);
        }
    }
#pragma unroll
    for (int i=0;i<4;i++) {
        float4 v = make_float4(acc[i][0],acc[i][1],acc[i][2],acc[i][3]);
        *(float4*)&g_part1[(s*NB + m0 + i)*G1 + jb + n0] = v;
    }
}

// ---------------- cell1: reduce partials + LSTM cell, writes h1 into g_act ----------------
__global__ __launch_bounds__(256) void kCell1(int t)
{
    int id = blockIdx.x*256 + threadIdx.x;   // < 32768
    int n = id >> 10, u = id & 1023;
    const float* xg = &g_Xg[(t*NB + n)*G1];
    float gi = xg[u], gf = xg[u+1024], gg = xg[u+2048], go = xg[u+3072];
#pragma unroll
    for (int s=0;s<4;s++) {
        const float* p = &g_part1[(s*NB + n)*G1];
        gi += p[u]; gf += p[u+1024]; gg += p[u+2048]; go += p[u+3072];
    }
    float i_ = sigm(gi), f_ = sigm(gf), g_ = tanhf(gg), o_ = sigm(go);
    float c = f_*g_c1[id] + i_*g_;
    g_c1[id] = c;
    g_act[n*KT + 128 + u] = o_*tanhf(c);
}

// ---------------- per-step LSTM2 GEMM partials (16 splits of 72) ----------------
//   k<1024 : h1 -> W_ih2[j*1024 + k], act = g_act[n][128+k]
//   k>=1024: h2 -> W_hh2[j*128 + (k-1024)], act = g_h2[n][k-1024]
__global__ __launch_bounds__(128) void kLstm2Gemm(const float* __restrict__ W_ih2,
                                                  const float* __restrict__ W_hh2)
{
    __shared__ float As[8][36];
    __shared__ float Ws[8][68];
    int tid = threadIdx.x;
    int jb = blockIdx.x * 64;
    int s  = blockIdx.y;
    int k0s = s * 72;
    int tm = tid & 7, tn = tid >> 3;
    int m0 = tm*4, n0 = tn*4;
    float acc[4][4];
#pragma unroll
    for (int i=0;i<4;i++)
#pragma unroll
        for (int j=0;j<4;j++) acc[i][j]=0.f;

    int an = tid >> 2, ak = (tid & 3)*2;
    int wj = tid >> 1, wk = (tid & 1)*4;

    for (int kc = k0s; kc < k0s + 72; kc += 8) {
        int ka = kc + ak;
        float2 av = (ka < 1024) ? *(const float2*)&g_act[an*KT + 128 + ka]
                                : *(const float2*)&g_h2[an*KSZ + ka - 1024];
        int kw = kc + wk;
        float4 wv = (kw < 1024) ? *(const float4*)&W_ih2[(jb+wj)*1024 + kw]
                                : *(const float4*)&W_hh2[(jb+wj)*128 + kw - 1024];
        __syncthreads();
        As[ak][an]   = av.x;
        As[ak+1][an] = av.y;
        Ws[wk+0][wj]=wv.x; Ws[wk+1][wj]=wv.y; Ws[wk+2][wj]=wv.z; Ws[wk+3][wj]=wv.w;
        __syncthreads();
#pragma unroll
        for (int kk = 0; kk < 8; kk++) {
            float4 a4 = *(const float4*)&As[kk][m0];
            float4 b4 = *(const float4*)&Ws[kk][n0];
            float aa[4]={a4.x,a4.y,a4.z,a4.w};
            float bbv[4]={b4.x,b4.y,b4.z,b4.w};
#pragma unroll
            for (int i=0;i<4;i++)
#pragma unroll
                for (int j=0;j<4;j++) acc[i][j] = fmaf(aa[i], bbv[j], acc[i][j]);
        }
    }
#pragma unroll
    for (int i=0;i<4;i++) {
        float4 v = make_float4(acc[i][0],acc[i][1],acc[i][2],acc[i][3]);
        *(float4*)&g_part2[(s*NB + m0 + i)*G2 + jb + n0] = v;
    }
}

// ---------------- cell2 + attention (one block per batch row) ----------------
__global__ __launch_bounds__(256) void kCell2Attn(int t,
                                                  const float* __restrict__ key,
                                                  const float* __restrict__ values,
                                                  const int* __restrict__ enc_lens,
                                                  const float* __restrict__ b_ih2,
                                                  const float* __restrict__ b_hh2)
{
    int n = blockIdx.x, tid = threadIdx.x;
    __shared__ float h2s[128];
    __shared__ float es[512];
    __shared__ float red[256];
    __shared__ float cs[2][128];

    if (tid < 128) {
        int u = tid;
        float g4[4];
#pragma unroll
        for (int g = 0; g < 4; g++) {
            int j = g*128 + u;
            float a = b_ih2[j] + b_hh2[j];
#pragma unroll
            for (int s = 0; s < 16; s++) a += g_part2[(s*NB + n)*G2 + j];
            g4[g] = a;
        }
        float i_ = sigm(g4[0]), f_ = sigm(g4[1]), gg = tanhf(g4[2]), o_ = sigm(g4[3]);
        float c = f_*g_c2[n*KSZ + u] + i_*gg;
        g_c2[n*KSZ + u] = c;
        float h = o_*tanhf(c);
        h2s[u] = h;
        g_h2[n*KSZ + u] = h;
    }
    __syncthreads();

    int warp = tid >> 5, lane = tid & 31;
    int len = enc_lens[n];
    const float4* h24 = (const float4*)h2s;
    float4 hv = h24[lane];
    for (int te = warp; te < TE; te += 8) {
        const float4* kp = (const float4*)&key[(n*TE + te)*KSZ];
        float4 kv = kp[lane];
        float p = kv.x*hv.x + kv.y*hv.y + kv.z*hv.z + kv.w*hv.w;
        p += __shfl_xor_sync(0xffffffffu, p, 16);
        p += __shfl_xor_sync(0xffffffffu, p, 8);
        p += __shfl_xor_sync(0xffffffffu, p, 4);
        p += __shfl_xor_sync(0xffffffffu, p, 2);
        p += __shfl_xor_sync(0xffffffffu, p, 1);
        if (lane == 0) es[te] = (te >= len) ? -1.0e9f : p;
    }
    __syncthreads();

    // softmax over 512
    float m = fmaxf(es[tid], es[tid + 256]);
    red[tid] = m;
    __syncthreads();
    for (int st = 128; st > 0; st >>= 1) {
        if (tid < st) red[tid] = fmaxf(red[tid], red[tid + st]);
        __syncthreads();
    }
    float mx = red[0];
    __syncthreads();
    float p0 = expf(es[tid] - mx);
    float p1 = expf(es[tid + 256] - mx);
    es[tid] = p0; es[tid + 256] = p1;
    red[tid] = p0 + p1;
    __syncthreads();
    for (int st = 128; st > 0; st >>= 1) {
        if (tid < st) red[tid] += red[tid + st];
        __syncthreads();
    }
    float inv = 1.0f / red[0];

    // context: ctx[v] = inv * sum_t es[t] * values[n][t][v]
    int v = tid & 127, half = tid >> 7;
    float acc = 0.f;
    int tb = half * 256;
#pragma unroll 4
    for (int te = tb; te < tb + 256; te++)
        acc += es[te] * values[(n*TE + te)*VSZ + v];
    cs[half][v] = acc;
    __syncthreads();
    if (tid < 128) {
        float ctx = (cs[0][tid] + cs[1][tid]) * inv;
        g_act[n*KT + tid] = ctx;
        float* hc = &g_h2ctx[(t*NB + n)*256];
        hc[tid]       = h2s[tid];
        hc[128 + tid] = ctx;
    }
}

// ---------------- launch ----------------
extern "C" void kernel_launch(void* const* d_in, const int* in_sizes, int n_in,
                              void* d_out, int out_size)
{
    const float* key    = (const float*)d_in[0];
    const float* values = (const float*)d_in[1];
    const int*   elens  = (const int*)  d_in[2];
    const int*   text   = (const int*)  d_in[3];
    const float* emb    = (const float*)d_in[4];
    const float* W_ih1  = (const float*)d_in[5];
    const float* W_hh1  = (const float*)d_in[6];
    const float* b_ih1  = (const float*)d_in[7];
    const float* b_hh1  = (const float*)d_in[8];
    const float* W_ih2  = (const float*)d_in[9];
    const float* W_hh2  = (const float*)d_in[10];
    const float* b_ih2  = (const float*)d_in[11];
    const float* b_out  = (const float*)d_in[14];
    const float* W_out  = (const float*)d_in[13];
    const float* b_hh2  = (const float*)d_in[12];
    float* out = (float*)d_out;

    // init: 4096 blocks for embedding + 304 blocks for state init
    kInit<<<LD*NB + 304, 256>>>(text, emb, values);

    // precompute Xg = X @ W_ih1[:, :256]^T + b_ih1 + b_hh1
    {
        float* gXg; cudaGetSymbolAddress((void**)&gXg, g_Xg);
        float* gX;  cudaGetSymbolAddress((void**)&gX, g_X);
        kGemmBig<384,0><<<dim3(G1/64, (LD*NB)/128), 256>>>(gX, W_ih1, b_ih1, b_hh1, gXg, G1);
    }

    for (int t = 0; t < LD; t++) {
        kLstm1Gemm<<<dim3(32, 4), 256>>>(W_ih1, W_hh1);
        kCell1<<<128, 256>>>(t);
        kLstm2Gemm<<<dim3(8, 16), 128>>>(W_ih2, W_hh2);
        kCell2Attn<<<32, 256>>>(t, key, values, elens, b_ih2, b_hh2);
    }

    // output logits: [h2,ctx] @ W_out^T + b_out, remapped to (n, t, v)
    {
        float* gHC; cudaGetSymbolAddress((void**)&gHC, g_h2ctx);
        kGemmBig<256,1><<<dim3(VV/64, (LD*NB)/128), 256>>>(gHC, W_out, b_out, (const float*)0, out, VV);
    }
}